// round 9
// baseline (speedup 1.0000x reference)
#include <cuda_runtime.h>
#include <cstdint>
#include <cstddef>

#define B_   16
#define CI_  32
#define HH   224
#define WW   224
#define CO_  32
#define OH_  222
#define OW_  222

// converted operands: per cell 32 words, fragment-vectorized order:
//   uint4[ch*4 + t] = { hi_{ch*8+t}, hi_{ch*8+t+4}, lo_{ch*8+t}, lo_{ch*8+t+4} }
// where pair p = ch*8 + q holds ci {2p, 2p+1}.
static __device__ __align__(16) unsigned int g_xcvt[(size_t)B_ * HH * WW * 32];
static __device__ __align__(16) unsigned int g_wcvt[9 * CO_ * 32];

#define THREADS 512
#define XT 2
#define YT 56           // ceil(222/4)
#define TROWS 6
#define TCOLS 136
#define SA_PLANE (TROWS * TCOLS * 16)       // 13056 words
#define SB_PLANE (9 * CO_ * 16)             // 4608 words
#define SMEM_WORDS (2 * SA_PLANE + 2 * SB_PLANE)   // 35328
#define SMEM_BYTES (SMEM_WORDS * 4)                // 141312

__device__ __forceinline__ unsigned pack_hi_trunc(unsigned u0, unsigned u1) {
    unsigned d;  // {lo16: u0>>16, hi16: u1>>16}
    asm("prmt.b32 %0, %1, %2, 0x7632;" : "=r"(d) : "r"(u0), "r"(u1));
    return d;
}
__device__ __forceinline__ unsigned pack_bf16x2(float even, float odd) {
    unsigned d;
    asm("cvt.rn.bf16x2.f32 %0, %1, %2;" : "=r"(d) : "f"(odd), "f"(even));
    return d;
}
__device__ __forceinline__ void mma_bf16(float* c, unsigned a0, unsigned a1,
                                         unsigned a2, unsigned a3,
                                         unsigned b0, unsigned b1) {
    asm volatile(
        "mma.sync.aligned.m16n8k16.row.col.f32.bf16.bf16.f32 "
        "{%0,%1,%2,%3}, {%4,%5,%6,%7}, {%8,%9}, {%0,%1,%2,%3};"
        : "+f"(c[0]), "+f"(c[1]), "+f"(c[2]), "+f"(c[3])
        : "r"(a0), "r"(a1), "r"(a2), "r"(a3), "r"(b0), "r"(b1));
}

__device__ __forceinline__ void emit_cell(uint4* d4, const unsigned* hw, const unsigned* lw) {
    #pragma unroll
    for (int ch = 0; ch < 2; ++ch)
        #pragma unroll
        for (int t = 0; t < 4; ++t)
            d4[ch * 4 + t] = make_uint4(hw[ch * 8 + t], hw[ch * 8 + t + 4],
                                        lw[ch * 8 + t], lw[ch * 8 + t + 4]);
}

// ---- pre-pass: convert x (and, in the tail block, w) ----
#define XBLOCKS ((B_ * HH * 7 * 32) / 256)     // 3136
__global__ void __launch_bounds__(256) cvt_xw(const float* __restrict__ x,
                                              const float* __restrict__ w) {
    if (blockIdx.x == XBLOCKS) {               // ---- weights (288 rows, 256 threads)
        for (int r = threadIdx.x; r < 288; r += 256) {   // FIX: loop, not single r
            const int tap = r >> 5, co = r & 31;
            unsigned hw[16], lw[16];
            #pragma unroll
            for (int p = 0; p < 16; ++p) {
                float v0 = __ldg(&w[co * 288 + (2 * p) * 9 + tap]);
                float v1 = __ldg(&w[co * 288 + (2 * p + 1) * 9 + tap]);
                unsigned u0 = __float_as_uint(v0), u1 = __float_as_uint(v1);
                hw[p] = pack_hi_trunc(u0, u1);
                lw[p] = pack_bf16x2(v0 - __uint_as_float(u0 & 0xffff0000u),
                                    v1 - __uint_as_float(u1 & 0xffff0000u));
            }
            emit_cell((uint4*)(g_wcvt + (size_t)r * 32), hw, lw);
        }
        return;
    }
    // ---- x
    const int lane = threadIdx.x & 31;
    const int W    = (blockIdx.x * 256 + threadIdx.x) >> 5;
    const int wb   = W % 7;
    const int h    = (W / 7) % HH;
    const int b    = W / (7 * HH);
    const int iw   = wb * 32 + lane;

    unsigned hw[16], lw[16];
    #pragma unroll
    for (int p = 0; p < 16; ++p) {
        size_t i0 = (((size_t)b * CI_ + 2 * p) * HH + h) * WW + iw;
        float v0 = __ldg(&x[i0]);
        float v1 = __ldg(&x[i0 + (size_t)HH * WW]);
        unsigned u0 = __float_as_uint(v0), u1 = __float_as_uint(v1);
        hw[p] = pack_hi_trunc(u0, u1);
        lw[p] = pack_bf16x2(v0 - __uint_as_float(u0 & 0xffff0000u),
                            v1 - __uint_as_float(u1 & 0xffff0000u));
    }
    emit_cell((uint4*)(g_xcvt + (((size_t)b * HH + h) * WW + iw) * 32), hw, lw);
}

// ---- main: implicit-GEMM conv, fragment loads as LDS.128 ----
__global__ void __launch_bounds__(THREADS, 1)
conv3x3_mma(const float* __restrict__ bias, float* __restrict__ out) {
    extern __shared__ unsigned smw[];
    unsigned* sA0 = smw;                        // A ch0 plane [cell][16]
    unsigned* sA1 = smw + SA_PLANE;             // A ch1
    unsigned* sB0 = smw + 2 * SA_PLANE;         // B ch0 [row][16]
    unsigned* sB1 = sB0 + SB_PLANE;

    const int tid = threadIdx.x;
    const int blk = blockIdx.x;
    const int bx  = blk & 1;
    const int by  = (blk >> 1) % YT;
    const int b   = blk / (2 * YT);
    const int px0 = bx ? 94 : 0;
    const int oh0 = by * 4;

    // ---- copy B: 288 rows x 8 subs (16B); sub 0-3 -> ch0 plane, 4-7 -> ch1
    for (int c = tid; c < 288 * 8; c += THREADS) {
        int row = c >> 3, sub = c & 7;
        uint4 v = *(const uint4*)(g_wcvt + (size_t)row * 32 + sub * 4);
        unsigned* dst = (sub < 4 ? sB0 : sB1) + row * 16 + (sub & 3) * 4;
        *(uint4*)dst = v;
    }
    // ---- copy A tile: 816 cells x 8 subs, zero-fill OOB
    for (int c = tid; c < TROWS * TCOLS * 8; c += THREADS) {
        int cell = c >> 3, sub = c & 7;
        int trow = cell / TCOLS, col = cell % TCOLS;
        int ih = oh0 + trow, iw = px0 + col;
        uint4 v = make_uint4(0, 0, 0, 0);
        if (ih < HH && iw < WW)
            v = *(const uint4*)(g_xcvt + (((size_t)b * HH + ih) * WW + iw) * 32 + sub * 4);
        unsigned* dst = (sub < 4 ? sA0 : sA1) + cell * 16 + (sub & 3) * 4;
        *(uint4*)dst = v;
    }
    __syncthreads();

    const int lane = tid & 31;
    const int wid  = tid >> 5;
    const int g = lane >> 2, t = lane & 3;
    const int orow = wid & 3;
    const int mq   = wid >> 2;

    float acc[2][4][4];
    #pragma unroll
    for (int mt = 0; mt < 2; mt++)
        #pragma unroll
        for (int nt = 0; nt < 4; nt++)
            #pragma unroll
            for (int i = 0; i < 4; i++) acc[mt][nt][i] = 0.f;

    const unsigned* sAc[2] = { sA0, sA1 };
    const unsigned* sBc[2] = { sB0, sB1 };

    #pragma unroll 1
    for (int ky = 0; ky < 3; ++ky) {
        #pragma unroll
        for (int kx = 0; kx < 3; ++kx) {
            #pragma unroll
            for (int ch = 0; ch < 2; ++ch) {
                // B frags: one LDS.128 per nt -> [b0h, b1h, b0l, b1l]
                const unsigned* bp = sBc[ch] + (((ky * 3 + kx) * 32) + g) * 16 + t * 4;
                uint4 bf[4];
                #pragma unroll
                for (int nt = 0; nt < 4; ++nt)
                    bf[nt] = *(const uint4*)(bp + nt * (8 * 16));

                // A frags: per mt two LDS.128 -> pixel rows g and g+8
                const unsigned* ap = sAc[ch]
                    + (((orow + ky) * TCOLS + mq * 32 + kx + g)) * 16 + t * 4;
                #pragma unroll
                for (int mt = 0; mt < 2; ++mt) {
                    uint4 aL = *(const uint4*)(ap + mt * (16 * 16));       // [a0h,a2h,a0l,a2l]
                    uint4 aH = *(const uint4*)(ap + (mt * 16 + 8) * 16);   // [a1h,a3h,a1l,a3l]
                    #pragma unroll
                    for (int nt = 0; nt < 4; ++nt) {
                        mma_bf16(acc[mt][nt], aL.x, aH.x, aL.y, aH.y, bf[nt].x, bf[nt].y); // hh
                        mma_bf16(acc[mt][nt], aL.x, aH.x, aL.y, aH.y, bf[nt].z, bf[nt].w); // h*l
                        mma_bf16(acc[mt][nt], aL.z, aH.z, aL.w, aH.w, bf[nt].x, bf[nt].y); // l*h
                    }
                }
            }
        }
    }

    // ---- epilogue
    const int oy = oh0 + orow;
    if (oy < OH_) {
        #pragma unroll
        for (int nt = 0; nt < 4; ++nt) {
            const int co0 = nt * 8 + t * 2;
            const float bs0 = __ldg(&bias[co0]);
            const float bs1 = __ldg(&bias[co0 + 1]);
            float* o0 = out + (((size_t)b * CO_ + co0)     * OH_ + oy) * OW_;
            float* o1 = out + (((size_t)b * CO_ + co0 + 1) * OH_ + oy) * OW_;
            #pragma unroll
            for (int mt = 0; mt < 2; ++mt) {
                const int pl = px0 + mq * 32 + mt * 16 + g;
                o0[pl]     = acc[mt][nt][0] + bs0;
                o1[pl]     = acc[mt][nt][1] + bs1;
                o0[pl + 8] = acc[mt][nt][2] + bs0;
                o1[pl + 8] = acc[mt][nt][3] + bs1;
            }
        }
    }
}

extern "C" void kernel_launch(void* const* d_in, const int* in_sizes, int n_in,
                              void* d_out, int out_size)
{
    const float* x    = (const float*)d_in[0];
    const float* w    = (const float*)d_in[1];
    const float* bias = (const float*)d_in[2];
    float* out        = (float*)d_out;

    cvt_xw<<<XBLOCKS + 1, 256>>>(x, w);

    cudaFuncSetAttribute(conv3x3_mma,
                         cudaFuncAttributeMaxDynamicSharedMemorySize, SMEM_BYTES);
    conv3x3_mma<<<B_ * YT * XT, THREADS, SMEM_BYTES>>>(bias, out);
}

// round 10
// speedup vs baseline: 1.0891x; 1.0891x over previous
#include <cuda_runtime.h>
#include <cstdint>
#include <cstddef>

#define B_   16
#define CI_  32
#define HH   224
#define WW   224
#define CO_  32
#define OH_  222
#define OW_  222

// converted operands: per cell 32 words, fragment-vectorized order:
//   uint4[ch*4 + t] = { hi_{ch*8+t}, hi_{ch*8+t+4}, lo_{ch*8+t}, lo_{ch*8+t+4} }
static __device__ __align__(16) unsigned int g_xcvt[(size_t)B_ * HH * WW * 32];
static __device__ __align__(16) unsigned int g_wcvt[9 * CO_ * 32];

// CTA = 256 thr = 8 warps; tile = 2 output rows x 128 px x 32 co.
// warp: orow = wid&1, mq = wid>>1 (32 px each).
#define THREADS 256
#define XT 2
#define YT 111          // 222 / 2, exact
#define TROWS 4         // 2 output rows + 2 halo (always in range vertically)
#define TCOLS 136
#define SA_PLANE (TROWS * TCOLS * 16)       // 8704 words
#define SB_PLANE (9 * CO_ * 16)             // 4608 words
#define SMEM_WORDS (2 * SA_PLANE + 2 * SB_PLANE)   // 26624
#define SMEM_BYTES (SMEM_WORDS * 4)                // 106496 -> 2 CTAs/SM

__device__ __forceinline__ unsigned pack_hi_trunc(unsigned u0, unsigned u1) {
    unsigned d;
    asm("prmt.b32 %0, %1, %2, 0x7632;" : "=r"(d) : "r"(u0), "r"(u1));
    return d;
}
__device__ __forceinline__ unsigned pack_bf16x2(float even, float odd) {
    unsigned d;
    asm("cvt.rn.bf16x2.f32 %0, %1, %2;" : "=r"(d) : "f"(odd), "f"(even));
    return d;
}
__device__ __forceinline__ void mma_bf16(float* c, unsigned a0, unsigned a1,
                                         unsigned a2, unsigned a3,
                                         unsigned b0, unsigned b1) {
    asm volatile(
        "mma.sync.aligned.m16n8k16.row.col.f32.bf16.bf16.f32 "
        "{%0,%1,%2,%3}, {%4,%5,%6,%7}, {%8,%9}, {%0,%1,%2,%3};"
        : "+f"(c[0]), "+f"(c[1]), "+f"(c[2]), "+f"(c[3])
        : "r"(a0), "r"(a1), "r"(a2), "r"(a3), "r"(b0), "r"(b1));
}

__device__ __forceinline__ void emit_cell(uint4* d4, const unsigned* hw, const unsigned* lw) {
    #pragma unroll
    for (int ch = 0; ch < 2; ++ch)
        #pragma unroll
        for (int t = 0; t < 4; ++t)
            d4[ch * 4 + t] = make_uint4(hw[ch * 8 + t], hw[ch * 8 + t + 4],
                                        lw[ch * 8 + t], lw[ch * 8 + t + 4]);
}

// ---- pre-pass: convert x (and, in the tail block, w) ----
#define XBLOCKS ((B_ * HH * 7 * 32) / 256)     // 3136
__global__ void __launch_bounds__(256) cvt_xw(const float* __restrict__ x,
                                              const float* __restrict__ w) {
    if (blockIdx.x == XBLOCKS) {               // ---- weights
        for (int r = threadIdx.x; r < 288; r += 256) {
            const int tap = r >> 5, co = r & 31;
            unsigned hw[16], lw[16];
            #pragma unroll
            for (int p = 0; p < 16; ++p) {
                float v0 = __ldg(&w[co * 288 + (2 * p) * 9 + tap]);
                float v1 = __ldg(&w[co * 288 + (2 * p + 1) * 9 + tap]);
                unsigned u0 = __float_as_uint(v0), u1 = __float_as_uint(v1);
                hw[p] = pack_hi_trunc(u0, u1);
                lw[p] = pack_bf16x2(v0 - __uint_as_float(u0 & 0xffff0000u),
                                    v1 - __uint_as_float(u1 & 0xffff0000u));
            }
            emit_cell((uint4*)(g_wcvt + (size_t)r * 32), hw, lw);
        }
        return;
    }
    const int lane = threadIdx.x & 31;
    const int W    = (blockIdx.x * 256 + threadIdx.x) >> 5;
    const int wb   = W % 7;
    const int h    = (W / 7) % HH;
    const int b    = W / (7 * HH);
    const int iw   = wb * 32 + lane;

    unsigned hw[16], lw[16];
    #pragma unroll
    for (int p = 0; p < 16; ++p) {
        size_t i0 = (((size_t)b * CI_ + 2 * p) * HH + h) * WW + iw;
        float v0 = __ldg(&x[i0]);
        float v1 = __ldg(&x[i0 + (size_t)HH * WW]);
        unsigned u0 = __float_as_uint(v0), u1 = __float_as_uint(v1);
        hw[p] = pack_hi_trunc(u0, u1);
        lw[p] = pack_bf16x2(v0 - __uint_as_float(u0 & 0xffff0000u),
                            v1 - __uint_as_float(u1 & 0xffff0000u));
    }
    emit_cell((uint4*)(g_xcvt + (((size_t)b * HH + h) * WW + iw) * 32), hw, lw);
}

// ---- main: implicit-GEMM conv, 2 CTAs/SM for load/compute overlap ----
__global__ void __launch_bounds__(THREADS, 2)
conv3x3_mma(const float* __restrict__ bias, float* __restrict__ out) {
    extern __shared__ unsigned smw[];
    unsigned* sA0 = smw;                        // A ch0 plane [cell][16]
    unsigned* sA1 = smw + SA_PLANE;
    unsigned* sB0 = smw + 2 * SA_PLANE;         // B ch0 [row][16]
    unsigned* sB1 = sB0 + SB_PLANE;

    const int tid = threadIdx.x;
    const int blk = blockIdx.x;
    const int bx  = blk & 1;
    const int by  = (blk >> 1) % YT;
    const int b   = blk / (2 * YT);
    const int px0 = bx ? 94 : 0;
    const int oh0 = by * 2;

    // ---- copy B: 288 rows x 8 subs
    for (int c = tid; c < 288 * 8; c += THREADS) {
        int row = c >> 3, sub = c & 7;
        uint4 v = *(const uint4*)(g_wcvt + (size_t)row * 32 + sub * 4);
        unsigned* dst = (sub < 4 ? sB0 : sB1) + row * 16 + (sub & 3) * 4;
        *(uint4*)dst = v;
    }
    // ---- copy A tile: 544 cells x 8 subs (rows always in range; guard width only)
    for (int c = tid; c < TROWS * TCOLS * 8; c += THREADS) {
        int cell = c >> 3, sub = c & 7;
        int trow = cell / TCOLS, col = cell % TCOLS;
        int ih = oh0 + trow, iw = px0 + col;
        uint4 v = make_uint4(0, 0, 0, 0);
        if (iw < WW)
            v = *(const uint4*)(g_xcvt + (((size_t)b * HH + ih) * WW + iw) * 32 + sub * 4);
        unsigned* dst = (sub < 4 ? sA0 : sA1) + cell * 16 + (sub & 3) * 4;
        *(uint4*)dst = v;
    }
    __syncthreads();

    const int lane = tid & 31;
    const int wid  = tid >> 5;
    const int g = lane >> 2, t = lane & 3;
    const int orow = wid & 1;
    const int mq   = wid >> 1;      // 0..3

    float acc[2][4][4];
    #pragma unroll
    for (int mt = 0; mt < 2; mt++)
        #pragma unroll
        for (int nt = 0; nt < 4; nt++)
            #pragma unroll
            for (int i = 0; i < 4; i++) acc[mt][nt][i] = 0.f;

    const unsigned* sAc[2] = { sA0, sA1 };
    const unsigned* sBc[2] = { sB0, sB1 };

    #pragma unroll 1
    for (int ky = 0; ky < 3; ++ky) {
        #pragma unroll
        for (int kx = 0; kx < 3; ++kx) {
            #pragma unroll
            for (int ch = 0; ch < 2; ++ch) {
                const unsigned* bp = sBc[ch] + (((ky * 3 + kx) * 32) + g) * 16 + t * 4;
                uint4 bf[4];
                #pragma unroll
                for (int nt = 0; nt < 4; ++nt)
                    bf[nt] = *(const uint4*)(bp + nt * (8 * 16));

                const unsigned* ap = sAc[ch]
                    + (((orow + ky) * TCOLS + mq * 32 + kx + g)) * 16 + t * 4;
                #pragma unroll
                for (int mt = 0; mt < 2; ++mt) {
                    uint4 aL = *(const uint4*)(ap + mt * (16 * 16));
                    uint4 aH = *(const uint4*)(ap + (mt * 16 + 8) * 16);
                    #pragma unroll
                    for (int nt = 0; nt < 4; ++nt) {
                        mma_bf16(acc[mt][nt], aL.x, aH.x, aL.y, aH.y, bf[nt].x, bf[nt].y);
                        mma_bf16(acc[mt][nt], aL.x, aH.x, aL.y, aH.y, bf[nt].z, bf[nt].w);
                        mma_bf16(acc[mt][nt], aL.z, aH.z, aL.w, aH.w, bf[nt].x, bf[nt].y);
                    }
                }
            }
        }
    }

    // ---- epilogue (rows always in range: 222 = 2*111)
    const int oy = oh0 + orow;
    #pragma unroll
    for (int nt = 0; nt < 4; ++nt) {
        const int co0 = nt * 8 + t * 2;
        const float bs0 = __ldg(&bias[co0]);
        const float bs1 = __ldg(&bias[co0 + 1]);
        float* o0 = out + (((size_t)b * CO_ + co0)     * OH_ + oy) * OW_;
        float* o1 = out + (((size_t)b * CO_ + co0 + 1) * OH_ + oy) * OW_;
        #pragma unroll
        for (int mt = 0; mt < 2; ++mt) {
            const int pl = px0 + mq * 32 + mt * 16 + g;
            o0[pl]     = acc[mt][nt][0] + bs0;
            o1[pl]     = acc[mt][nt][1] + bs1;
            o0[pl + 8] = acc[mt][nt][2] + bs0;
            o1[pl + 8] = acc[mt][nt][3] + bs1;
        }
    }
}

extern "C" void kernel_launch(void* const* d_in, const int* in_sizes, int n_in,
                              void* d_out, int out_size)
{
    const float* x    = (const float*)d_in[0];
    const float* w    = (const float*)d_in[1];
    const float* bias = (const float*)d_in[2];
    float* out        = (float*)d_out;

    cvt_xw<<<XBLOCKS + 1, 256>>>(x, w);

    cudaFuncSetAttribute(conv3x3_mma,
                         cudaFuncAttributeMaxDynamicSharedMemorySize, SMEM_BYTES);
    conv3x3_mma<<<B_ * YT * XT, THREADS, SMEM_BYTES>>>(bias, out);
}

// round 11
// speedup vs baseline: 1.4797x; 1.3587x over previous
#include <cuda_runtime.h>
#include <cstdint>
#include <cstddef>

#define B_   16
#define CI_  32
#define HH   224
#define WW   224
#define CO_  32
#define OH_  222
#define OW_  222

// converted operands: per cell 32 words, fragment-vectorized order:
//   uint4[ch*4 + t] = { hi_{ch*8+t}, hi_{ch*8+t+4}, lo_{ch*8+t}, lo_{ch*8+t+4} }
static __device__ __align__(16) unsigned int g_xcvt[(size_t)B_ * HH * WW * 32];
static __device__ __align__(16) unsigned int g_wcvt[9 * CO_ * 32];

#define THREADS 256
#define XT 2
#define YT 111          // 222 / 2
#define TROWS 4
#define TCOLS 136
#define SA_PLANE (TROWS * TCOLS * 16)       // 8704 words
#define SB_PLANE (9 * CO_ * 16)             // 4608 words
#define SMEM_WORDS (2 * SA_PLANE + 2 * SB_PLANE)   // 26624
#define SMEM_BYTES (SMEM_WORDS * 4)                // 106496 -> 2 CTAs/SM

__device__ __forceinline__ unsigned pack_hi_trunc(unsigned u0, unsigned u1) {
    unsigned d;
    asm("prmt.b32 %0, %1, %2, 0x7632;" : "=r"(d) : "r"(u0), "r"(u1));
    return d;
}
__device__ __forceinline__ unsigned pack_bf16x2(float even, float odd) {
    unsigned d;
    asm("cvt.rn.bf16x2.f32 %0, %1, %2;" : "=r"(d) : "f"(odd), "f"(even));
    return d;
}
__device__ __forceinline__ void mma_bf16(float* c, unsigned a0, unsigned a1,
                                         unsigned a2, unsigned a3,
                                         unsigned b0, unsigned b1) {
    asm volatile(
        "mma.sync.aligned.m16n8k16.row.col.f32.bf16.bf16.f32 "
        "{%0,%1,%2,%3}, {%4,%5,%6,%7}, {%8,%9}, {%0,%1,%2,%3};"
        : "+f"(c[0]), "+f"(c[1]), "+f"(c[2]), "+f"(c[3])
        : "r"(a0), "r"(a1), "r"(a2), "r"(a3), "r"(b0), "r"(b1));
}
__device__ __forceinline__ void cp16(unsigned dst, const void* src, int nbytes) {
    asm volatile("cp.async.cg.shared.global [%0], [%1], 16, %2;"
                 :: "r"(dst), "l"(src), "r"(nbytes) : "memory");
}
#define CP_COMMIT() asm volatile("cp.async.commit_group;" ::: "memory")
#define CP_WAIT(n)  asm volatile("cp.async.wait_group %0;" :: "n"(n) : "memory")

__device__ __forceinline__ void emit_cell(uint4* d4, const unsigned* hw, const unsigned* lw) {
    #pragma unroll
    for (int ch = 0; ch < 2; ++ch)
        #pragma unroll
        for (int t = 0; t < 4; ++t)
            d4[ch * 4 + t] = make_uint4(hw[ch * 8 + t], hw[ch * 8 + t + 4],
                                        lw[ch * 8 + t], lw[ch * 8 + t + 4]);
}

// ---- pre-pass: convert x (and, in the tail block, w) ----
#define XBLOCKS ((B_ * HH * 7 * 32) / 256)     // 3136
__global__ void __launch_bounds__(256) cvt_xw(const float* __restrict__ x,
                                              const float* __restrict__ w) {
    if (blockIdx.x == XBLOCKS) {
        for (int r = threadIdx.x; r < 288; r += 256) {
            const int tap = r >> 5, co = r & 31;
            unsigned hw[16], lw[16];
            #pragma unroll
            for (int p = 0; p < 16; ++p) {
                float v0 = __ldg(&w[co * 288 + (2 * p) * 9 + tap]);
                float v1 = __ldg(&w[co * 288 + (2 * p + 1) * 9 + tap]);
                unsigned u0 = __float_as_uint(v0), u1 = __float_as_uint(v1);
                hw[p] = pack_hi_trunc(u0, u1);
                lw[p] = pack_bf16x2(v0 - __uint_as_float(u0 & 0xffff0000u),
                                    v1 - __uint_as_float(u1 & 0xffff0000u));
            }
            emit_cell((uint4*)(g_wcvt + (size_t)r * 32), hw, lw);
        }
        return;
    }
    const int lane = threadIdx.x & 31;
    const int W    = (blockIdx.x * 256 + threadIdx.x) >> 5;
    const int wb   = W % 7;
    const int h    = (W / 7) % HH;
    const int b    = W / (7 * HH);
    const int iw   = wb * 32 + lane;

    unsigned hw[16], lw[16];
    #pragma unroll
    for (int p = 0; p < 16; ++p) {
        size_t i0 = (((size_t)b * CI_ + 2 * p) * HH + h) * WW + iw;
        float v0 = __ldg(&x[i0]);
        float v1 = __ldg(&x[i0 + (size_t)HH * WW]);
        unsigned u0 = __float_as_uint(v0), u1 = __float_as_uint(v1);
        hw[p] = pack_hi_trunc(u0, u1);
        lw[p] = pack_bf16x2(v0 - __uint_as_float(u0 & 0xffff0000u),
                            v1 - __uint_as_float(u1 & 0xffff0000u));
    }
    emit_cell((uint4*)(g_xcvt + (((size_t)b * HH + h) * WW + iw) * 32), hw, lw);
}

// compute all 9 taps for one ci-half plane (216 MMAs per warp)
__device__ __forceinline__ void compute_plane(const unsigned* __restrict__ sA,
                                              const unsigned* __restrict__ sB,
                                              float acc[2][4][4],
                                              int orow, int mq, int g, int t) {
    #pragma unroll
    for (int ky = 0; ky < 3; ++ky) {
        #pragma unroll
        for (int kx = 0; kx < 3; ++kx) {
            const unsigned* bp = sB + (((ky * 3 + kx) * 32) + g) * 16 + t * 4;
            uint4 bf[4];
            #pragma unroll
            for (int nt = 0; nt < 4; ++nt)
                bf[nt] = *(const uint4*)(bp + nt * (8 * 16));

            const unsigned* ap = sA + (((orow + ky) * TCOLS + mq * 32 + kx + g)) * 16 + t * 4;
            #pragma unroll
            for (int mt = 0; mt < 2; ++mt) {
                uint4 aL = *(const uint4*)(ap + mt * (16 * 16));
                uint4 aH = *(const uint4*)(ap + (mt * 16 + 8) * 16);
                #pragma unroll
                for (int nt = 0; nt < 4; ++nt) {
                    mma_bf16(acc[mt][nt], aL.x, aH.x, aL.y, aH.y, bf[nt].x, bf[nt].y);
                    mma_bf16(acc[mt][nt], aL.x, aH.x, aL.y, aH.y, bf[nt].z, bf[nt].w);
                    mma_bf16(acc[mt][nt], aL.z, aH.z, aL.w, aH.w, bf[nt].x, bf[nt].y);
                }
            }
        }
    }
}

// ---- main: implicit-GEMM conv, cp.async pipelined over the two ci-halves ----
__global__ void __launch_bounds__(THREADS, 2)
conv3x3_mma(const float* __restrict__ bias, float* __restrict__ out) {
    extern __shared__ unsigned smw[];
    unsigned* sA0 = smw;
    unsigned* sA1 = smw + SA_PLANE;
    unsigned* sB0 = smw + 2 * SA_PLANE;
    unsigned* sB1 = sB0 + SB_PLANE;
    const unsigned aA0 = (unsigned)__cvta_generic_to_shared(sA0);
    const unsigned aA1 = (unsigned)__cvta_generic_to_shared(sA1);
    const unsigned aB0 = (unsigned)__cvta_generic_to_shared(sB0);
    const unsigned aB1 = (unsigned)__cvta_generic_to_shared(sB1);

    const int tid = threadIdx.x;
    const int blk = blockIdx.x;
    const int bx  = blk & 1;
    const int by  = (blk >> 1) % YT;
    const int b   = blk / (2 * YT);
    const int px0 = bx ? 94 : 0;
    const int oh0 = by * 2;

    // ---- issue cp.async groups: plane 0, then plane 1 (shift/mask indexing only)
    #pragma unroll
    for (int ch = 0; ch < 2; ++ch) {
        const unsigned dB = ch ? aB1 : aB0;
        const unsigned dA = ch ? aA1 : aA0;
        const int so = ch * 16;                       // src word offset for this plane
        // B: 288 rows x 4 subs = 1152 chunks
        for (int i = tid; i < 288 * 4; i += THREADS) {
            int row = i >> 2, sub = i & 3;
            cp16(dB + (unsigned)(row * 64 + sub * 16),
                 g_wcvt + (size_t)row * 32 + so + sub * 4, 16);
        }
        // A: 4 rows x 136 cols x 4 subs
        #pragma unroll
        for (int trow = 0; trow < TROWS; ++trow) {
            const unsigned* gr = g_xcvt + (((size_t)b * HH + oh0 + trow) * WW) * 32;
            const unsigned dAr = dA + (unsigned)(trow * TCOLS * 64);
            for (int i = tid; i < TCOLS * 4; i += THREADS) {
                int col = i >> 2, sub = i & 3;
                int iw  = px0 + col;
                int ok  = (iw < WW);
                cp16(dAr + (unsigned)(col * 64 + sub * 16),
                     gr + (size_t)(ok ? iw : 0) * 32 + so + sub * 4, ok ? 16 : 0);
            }
        }
        CP_COMMIT();
    }

    const int lane = tid & 31;
    const int wid  = tid >> 5;
    const int g = lane >> 2, t = lane & 3;
    const int orow = wid & 1;
    const int mq   = wid >> 1;

    float acc[2][4][4];
    #pragma unroll
    for (int mt = 0; mt < 2; mt++)
        #pragma unroll
        for (int nt = 0; nt < 4; nt++)
            #pragma unroll
            for (int i = 0; i < 4; i++) acc[mt][nt][i] = 0.f;

    CP_WAIT(1);                 // plane 0 landed; plane 1 still in flight
    __syncthreads();
    compute_plane(sA0, sB0, acc, orow, mq, g, t);

    CP_WAIT(0);                 // plane 1 landed
    __syncthreads();
    compute_plane(sA1, sB1, acc, orow, mq, g, t);

    // ---- epilogue (rows always in range: 222 = 2*111)
    const int oy = oh0 + orow;
    #pragma unroll
    for (int nt = 0; nt < 4; ++nt) {
        const int co0 = nt * 8 + t * 2;
        const float bs0 = __ldg(&bias[co0]);
        const float bs1 = __ldg(&bias[co0 + 1]);
        float* o0 = out + (((size_t)b * CO_ + co0)     * OH_ + oy) * OW_;
        float* o1 = out + (((size_t)b * CO_ + co0 + 1) * OH_ + oy) * OW_;
        #pragma unroll
        for (int mt = 0; mt < 2; ++mt) {
            const int pl = px0 + mq * 32 + mt * 16 + g;
            o0[pl]     = acc[mt][nt][0] + bs0;
            o1[pl]     = acc[mt][nt][1] + bs1;
            o0[pl + 8] = acc[mt][nt][2] + bs0;
            o1[pl + 8] = acc[mt][nt][3] + bs1;
        }
    }
}

extern "C" void kernel_launch(void* const* d_in, const int* in_sizes, int n_in,
                              void* d_out, int out_size)
{
    const float* x    = (const float*)d_in[0];
    const float* w    = (const float*)d_in[1];
    const float* bias = (const float*)d_in[2];
    float* out        = (float*)d_out;

    cvt_xw<<<XBLOCKS + 1, 256>>>(x, w);

    cudaFuncSetAttribute(conv3x3_mma,
                         cudaFuncAttributeMaxDynamicSharedMemorySize, SMEM_BYTES);
    conv3x3_mma<<<B_ * YT * XT, THREADS, SMEM_BYTES>>>(bias, out);
}